// round 7
// baseline (speedup 1.0000x reference)
#include <cuda_runtime.h>
#include <math.h>
#include <stdint.h>

#define NLAYER 4
#define BB 2
#define TT 2048
#define CC 512
#define NH 8
#define HDIM 64
#define FF 2048
#define VOCAB 32000
#define MT (BB*TT)   // 4096 rows

// ---------------- scratch (device globals; no allocations allowed) ----------
__device__ float g_x   [(size_t)MT*CC];
__device__ float g_ln  [(size_t)MT*CC];
__device__ float g_q   [(size_t)MT*CC];
__device__ float g_k   [(size_t)MT*CC];
__device__ float g_v   [(size_t)MT*CC];
__device__ float g_attn[(size_t)MT*CC];
__device__ float g_ff  [(size_t)MT*FF];
__device__ float2 g_stats[(size_t)BB*NH*TT];   // per-row (m, l) from flash pass

// ---------------- helpers ----------------------------------------------------
__device__ __forceinline__ uint32_t f2tf32(float x) {
    uint32_t u;
    asm("cvt.rna.tf32.f32 %0, %1;" : "=r"(u) : "f"(x));
    return u;
}

__device__ __forceinline__ void mma_tf32(float* c, const uint32_t* a, const uint32_t* b) {
    asm volatile(
        "mma.sync.aligned.m16n8k8.row.col.f32.tf32.tf32.f32 "
        "{%0,%1,%2,%3}, {%4,%5,%6,%7}, {%8,%9}, {%0,%1,%2,%3};"
        : "+f"(c[0]), "+f"(c[1]), "+f"(c[2]), "+f"(c[3])
        : "r"(a[0]), "r"(a[1]), "r"(a[2]), "r"(a[3]), "r"(b[0]), "r"(b[1]));
}

__device__ __forceinline__ void cp16(void* sdst, const void* gsrc) {
    unsigned s = (unsigned)__cvta_generic_to_shared(sdst);
    asm volatile("cp.async.cg.shared.global [%0], [%1], 16;\n" :: "r"(s), "l"(gsrc));
}
__device__ __forceinline__ void cp_commit() { asm volatile("cp.async.commit_group;\n"); }
template<int N>
__device__ __forceinline__ void cp_wait() { asm volatile("cp.async.wait_group %0;\n" :: "n"(N)); }

// =============================================================================
// TF32 tensor-core GEMM core (NT). C[M,N] = A[M,K] @ W[N,K]^T
// CTA tile BM x BN x 32, 256 threads, double-buffered cp.async pipeline.
// EPI: 1 = +bias, 2 = +bias,relu, 3 = +bias,+residual
// =============================================================================
template<int EPI, int BM, int BN>
__device__ __forceinline__ void gemm_core(
    const float* __restrict__ A, const float* __restrict__ B,
    const float* __restrict__ bias, const float* __restrict__ res,
    float* __restrict__ C, int lda, int ldb, int ldc, int K)
{
    constexpr int WM   = BM / 64;
    constexpr int WN   = 8 / WM;
    constexpr int NCW  = BN / WN;
    constexpr int NT_  = NCW / 8;

    extern __shared__ float smem[];
    float* As = smem;                        // 2 * BM * 36
    float* Bs = smem + 2 * BM * 36;          // 2 * BN * 36

    const int tid  = threadIdx.x;
    const int lane = tid & 31, wid = tid >> 5;
    const int warpM = (WM == 1) ? 0 : (wid & 1);
    const int warpN = (WM == 1) ? wid : (wid >> 1);
    const int grp = lane >> 2, qd = lane & 3;

    const int row0 = blockIdx.y * BM;
    const int col0 = blockIdx.x * BN;

    float acc[4][NT_][4];
#pragma unroll
    for (int mt = 0; mt < 4; mt++)
#pragma unroll
        for (int nt = 0; nt < NT_; nt++)
#pragma unroll
            for (int i = 0; i < 4; i++) acc[mt][nt][i] = 0.f;

    auto loadA = [&](int buf, int k0) {
#pragma unroll
        for (int i = 0; i < BM / 32; i++) {
            int idx = i * 256 + tid;
            int r = idx >> 3, c4 = (idx & 7) << 2;
            cp16(As + buf * BM * 36 + r * 36 + c4,
                 A + (size_t)(row0 + r) * lda + k0 + c4);
        }
    };
    auto loadB = [&](int buf, int k0) {
#pragma unroll
        for (int i = 0; i < BN / 32; i++) {
            int idx = i * 256 + tid;
            int r = idx >> 3, c4 = (idx & 7) << 2;
            cp16(Bs + buf * BN * 36 + r * 36 + c4,
                 B + (size_t)(col0 + r) * ldb + k0 + c4);
        }
    };

    auto compute = [&](int buf) {
        const float* Ab = As + buf * BM * 36;
        const float* Bb = Bs + buf * BN * 36;
#pragma unroll
        for (int kt = 0; kt < 4; kt++) {
            uint32_t af[4][4];
#pragma unroll
            for (int mt = 0; mt < 4; mt++) {
                int r0 = warpM * 64 + mt * 16 + grp;
                af[mt][0] = f2tf32(Ab[(r0)     * 36 + kt * 8 + qd]);
                af[mt][1] = f2tf32(Ab[(r0 + 8) * 36 + kt * 8 + qd]);
                af[mt][2] = f2tf32(Ab[(r0)     * 36 + kt * 8 + qd + 4]);
                af[mt][3] = f2tf32(Ab[(r0 + 8) * 36 + kt * 8 + qd + 4]);
            }
            uint32_t bf[NT_][2];
#pragma unroll
            for (int nt = 0; nt < NT_; nt++) {
                int nb = warpN * NCW + nt * 8 + grp;
                bf[nt][0] = f2tf32(Bb[nb * 36 + kt * 8 + qd]);
                bf[nt][1] = f2tf32(Bb[nb * 36 + kt * 8 + qd + 4]);
            }
#pragma unroll
            for (int mt = 0; mt < 4; mt++)
#pragma unroll
                for (int nt = 0; nt < NT_; nt++)
                    mma_tf32(acc[mt][nt], af[mt], bf[nt]);
        }
    };

    const int nk = K >> 5;
    loadA(0, 0);  loadB(0, 0);  cp_commit();
    loadA(1, 32); loadB(1, 32); cp_commit();
    cp_wait<1>();
    __syncthreads();

    for (int kb = 0; kb < nk; kb++) {
        compute(kb & 1);
        __syncthreads();
        if (kb + 2 < nk) { loadA(kb & 1, (kb + 2) * 32); loadB(kb & 1, (kb + 2) * 32); }
        cp_commit();
        cp_wait<1>();
        __syncthreads();
    }

#pragma unroll
    for (int mt = 0; mt < 4; mt++)
#pragma unroll
        for (int nt = 0; nt < NT_; nt++) {
            int row = row0 + warpM * 64 + mt * 16 + grp;
            int col = col0 + warpN * NCW + nt * 8 + qd * 2;
#pragma unroll
            for (int half = 0; half < 2; half++) {
                int r = row + half * 8;
                float v0 = acc[mt][nt][half * 2 + 0];
                float v1 = acc[mt][nt][half * 2 + 1];
                v0 += bias[col]; v1 += bias[col + 1];
                if (EPI == 2) { v0 = fmaxf(v0, 0.f); v1 = fmaxf(v1, 0.f); }
                if (EPI == 3) {
                    v0 += res[(size_t)r * ldc + col];
                    v1 += res[(size_t)r * ldc + col + 1];
                }
                *(float2*)(C + (size_t)r * ldc + col) = make_float2(v0, v1);
            }
        }
}

template<int EPI, int BM, int BN>
__global__ void __launch_bounds__(256, 2)
gemm_tc_kernel(const float* __restrict__ A, const float* __restrict__ B,
               const float* __restrict__ bias, const float* __restrict__ res,
               float* __restrict__ C, int lda, int ldb, int ldc, int K) {
    gemm_core<EPI, BM, BN>(A, B, bias, res, C, lda, ldb, ldc, K);
}

// ---- fused QKV (z selects weight/bias/output) --------------------------------
template<int BM, int BN>
__global__ void __launch_bounds__(256, 2)
gemm_qkv_kernel(const float* __restrict__ A,
                const float* __restrict__ Wq, const float* __restrict__ Wk,
                const float* __restrict__ Wv,
                const float* __restrict__ bq, const float* __restrict__ bk,
                const float* __restrict__ bv,
                float* __restrict__ q, float* __restrict__ k, float* __restrict__ v) {
    int z = blockIdx.z;
    const float* B    = z == 0 ? Wq : (z == 1 ? Wk : Wv);
    const float* bias = z == 0 ? bq : (z == 1 ? bk : bv);
    float* C          = z == 0 ? q  : (z == 1 ? k  : v);
    gemm_core<1, BM, BN>(A, B, bias, nullptr, C, CC, CC, CC, CC);
}

// =============================================================================
// Flash attention pass 1: per (qtile=128, h, b): O = softmax(QK^T/8) V (online).
// 32-key tiles, single SMEM buffer, REGISTER PREFETCH of next tile's K/V:
//   sts(regs)->sync ; ldg(next)->regs ; compute ; sync
// LDG latency of tile kt+1 overlaps the 64 MMAs of tile kt.
// SMEM holds pre-converted tf32. 71 KB -> 2 CTAs/SM.
// =============================================================================
__global__ void __launch_bounds__(256, 2)
flash_kernel(const float* __restrict__ q, const float* __restrict__ k,
             const float* __restrict__ v, float* __restrict__ o) {
    constexpr int PQ = 68;   // Q/P row stride (%32==4 -> conflict-free)
    constexpr int PV = 72;   // V row stride
    constexpr int PP = 36;   // P row stride (32 cols + 4)
    constexpr int KT = 32;   // keys per tile
    constexpr int NKT = TT / KT;   // 64
    extern __shared__ uint32_t usm[];
    uint32_t* Qs = usm;                  // 128*68
    uint32_t* Ks = Qs + 128 * PQ;        // 32*68
    uint32_t* Vs = Ks + KT * PQ;         // 32*72
    uint32_t* Ps = Vs + KT * PV;         // 128*36

    const int qt = blockIdx.x, h = blockIdx.y, b = blockIdx.z;
    const int tid = threadIdx.x, lane = tid & 31, w = tid >> 5;
    const int grp = lane >> 2, qd = lane & 3;
    const int rbase = w * 16;

    const float* Qp = q + ((size_t)(b * TT) + qt * 128) * CC + h * 64;
    const float* Kp = k + (size_t)b * TT * CC + h * 64;
    const float* Vp = v + (size_t)b * TT * CC + h * 64;

    // stage Q, pre-scaled by 1/8 (exact), converted to tf32
#pragma unroll
    for (int i = 0; i < 8; i++) {
        int j = i * 256 + tid;
        int r = j >> 4, c4 = (j & 15) << 2;
        float4 t4 = *(const float4*)(Qp + (size_t)r * CC + c4);
        uint4 u;
        u.x = f2tf32(t4.x * 0.125f); u.y = f2tf32(t4.y * 0.125f);
        u.z = f2tf32(t4.z * 0.125f); u.w = f2tf32(t4.w * 0.125f);
        *(uint4*)(Qs + r * PQ + c4) = u;
    }

    // per-thread staging job coords (2 float4 each for K and V)
    const int jr0 = tid >> 4,        jc0 = (tid & 15) << 2;          // rows 0..15
    const int jr1 = (256 + tid) >> 4, jc1 = jc0;                      // rows 16..31

    float4 kreg[2], vreg[2];
    auto ldgKV = [&](int kt) {
        const float* Kt = Kp + (size_t)kt * KT * CC;
        const float* Vt = Vp + (size_t)kt * KT * CC;
        kreg[0] = *(const float4*)(Kt + (size_t)jr0 * CC + jc0);
        kreg[1] = *(const float4*)(Kt + (size_t)jr1 * CC + jc1);
        vreg[0] = *(const float4*)(Vt + (size_t)jr0 * CC + jc0);
        vreg[1] = *(const float4*)(Vt + (size_t)jr1 * CC + jc1);
    };
    auto stsKV = [&]() {
        uint4 u;
        u.x = f2tf32(kreg[0].x); u.y = f2tf32(kreg[0].y);
        u.z = f2tf32(kreg[0].z); u.w = f2tf32(kreg[0].w);
        *(uint4*)(Ks + jr0 * PQ + jc0) = u;
        u.x = f2tf32(kreg[1].x); u.y = f2tf32(kreg[1].y);
        u.z = f2tf32(kreg[1].z); u.w = f2tf32(kreg[1].w);
        *(uint4*)(Ks + jr1 * PQ + jc1) = u;
        u.x = f2tf32(vreg[0].x); u.y = f2tf32(vreg[0].y);
        u.z = f2tf32(vreg[0].z); u.w = f2tf32(vreg[0].w);
        *(uint4*)(Vs + jr0 * PV + jc0) = u;
        u.x = f2tf32(vreg[1].x); u.y = f2tf32(vreg[1].y);
        u.z = f2tf32(vreg[1].z); u.w = f2tf32(vreg[1].w);
        *(uint4*)(Vs + jr1 * PV + jc1) = u;
    };

    float oacc[8][4];
#pragma unroll
    for (int nt = 0; nt < 8; nt++)
#pragma unroll
        for (int i = 0; i < 4; i++) oacc[nt][i] = 0.f;
    float m0 = -1e30f, m1 = -1e30f, l0 = 0.f, l1 = 0.f;

    ldgKV(0);

    for (int kt = 0; kt < NKT; kt++) {
        stsKV();
        __syncthreads();            // tile kt ready (covers Q staging at kt=0)
        if (kt + 1 < NKT) ldgKV(kt + 1);   // overlaps with compute below

        // ---- S = Qs @ Ks^T  (16 rows x 32 keys) ----
        float sacc[4][4];
#pragma unroll
        for (int nt = 0; nt < 4; nt++)
#pragma unroll
            for (int i = 0; i < 4; i++) sacc[nt][i] = 0.f;
#pragma unroll
        for (int k8 = 0; k8 < 8; k8++) {
            uint32_t af[4];
            af[0] = Qs[(rbase + grp)     * PQ + k8 * 8 + qd];
            af[1] = Qs[(rbase + grp + 8) * PQ + k8 * 8 + qd];
            af[2] = Qs[(rbase + grp)     * PQ + k8 * 8 + qd + 4];
            af[3] = Qs[(rbase + grp + 8) * PQ + k8 * 8 + qd + 4];
#pragma unroll
            for (int nt = 0; nt < 4; nt++) {
                uint32_t bf[2];
                bf[0] = Ks[(nt * 8 + grp) * PQ + k8 * 8 + qd];
                bf[1] = Ks[(nt * 8 + grp) * PQ + k8 * 8 + qd + 4];
                mma_tf32(sacc[nt], af, bf);
            }
        }

        // ---- online softmax update ----
        float mx0 = -1e30f, mx1 = -1e30f;
#pragma unroll
        for (int nt = 0; nt < 4; nt++) {
            mx0 = fmaxf(mx0, fmaxf(sacc[nt][0], sacc[nt][1]));
            mx1 = fmaxf(mx1, fmaxf(sacc[nt][2], sacc[nt][3]));
        }
        mx0 = fmaxf(mx0, __shfl_xor_sync(0xffffffffu, mx0, 1));
        mx0 = fmaxf(mx0, __shfl_xor_sync(0xffffffffu, mx0, 2));
        mx1 = fmaxf(mx1, __shfl_xor_sync(0xffffffffu, mx1, 1));
        mx1 = fmaxf(mx1, __shfl_xor_sync(0xffffffffu, mx1, 2));
        float mn0 = fmaxf(m0, mx0), mn1 = fmaxf(m1, mx1);
        float f0 = __expf(m0 - mn0), f1 = __expf(m1 - mn1);
        m0 = mn0; m1 = mn1;
        float rs0 = 0.f, rs1 = 0.f;
#pragma unroll
        for (int nt = 0; nt < 4; nt++) {
            sacc[nt][0] = __expf(sacc[nt][0] - m0);
            sacc[nt][1] = __expf(sacc[nt][1] - m0);
            sacc[nt][2] = __expf(sacc[nt][2] - m1);
            sacc[nt][3] = __expf(sacc[nt][3] - m1);
            rs0 += sacc[nt][0] + sacc[nt][1];
            rs1 += sacc[nt][2] + sacc[nt][3];
        }
        rs0 += __shfl_xor_sync(0xffffffffu, rs0, 1);
        rs0 += __shfl_xor_sync(0xffffffffu, rs0, 2);
        rs1 += __shfl_xor_sync(0xffffffffu, rs1, 1);
        rs1 += __shfl_xor_sync(0xffffffffu, rs1, 2);
        l0 = l0 * f0 + rs0;
        l1 = l1 * f1 + rs1;
#pragma unroll
        for (int nt = 0; nt < 4; nt++) {
            oacc[nt][0] *= f0; oacc[nt][1] *= f0;
            oacc[nt][2] *= f1; oacc[nt][3] *= f1;
            oacc[nt + 4][0] *= f0; oacc[nt + 4][1] *= f0;
            oacc[nt + 4][2] *= f1; oacc[nt + 4][3] *= f1;
        }

        // ---- stage P (warp-private rows) as tf32 ----
#pragma unroll
        for (int nt = 0; nt < 4; nt++) {
            uint2 p0 = make_uint2(f2tf32(sacc[nt][0]), f2tf32(sacc[nt][1]));
            uint2 p1 = make_uint2(f2tf32(sacc[nt][2]), f2tf32(sacc[nt][3]));
            *(uint2*)(Ps + (rbase + grp)     * PP + nt * 8 + qd * 2) = p0;
            *(uint2*)(Ps + (rbase + grp + 8) * PP + nt * 8 + qd * 2) = p1;
        }
        __syncwarp();

        // ---- O += P @ V  (16 rows x 64 cols, K=32) ----
#pragma unroll
        for (int k8 = 0; k8 < 4; k8++) {
            uint32_t af[4];
            af[0] = Ps[(rbase + grp)     * PP + k8 * 8 + qd];
            af[1] = Ps[(rbase + grp + 8) * PP + k8 * 8 + qd];
            af[2] = Ps[(rbase + grp)     * PP + k8 * 8 + qd + 4];
            af[3] = Ps[(rbase + grp + 8) * PP + k8 * 8 + qd + 4];
#pragma unroll
            for (int nt = 0; nt < 8; nt++) {
                uint32_t bf[2];
                bf[0] = Vs[(k8 * 8 + qd)     * PV + nt * 8 + grp];
                bf[1] = Vs[(k8 * 8 + qd + 4) * PV + nt * 8 + grp];
                mma_tf32(oacc[nt], af, bf);
            }
        }
        __syncthreads();            // all warps done with tile kt buffers
    }

    // ---- epilogue: normalize + write O and stats ----
    float i0 = 1.f / l0, i1 = 1.f / l1;
    int row0 = qt * 128 + rbase + grp;
    float* Op = o + ((size_t)(b * TT) + row0) * CC + h * 64;
#pragma unroll
    for (int nt = 0; nt < 8; nt++) {
        *(float2*)(Op + nt * 8 + qd * 2) =
            make_float2(oacc[nt][0] * i0, oacc[nt][1] * i0);
        *(float2*)(Op + (size_t)8 * CC + nt * 8 + qd * 2) =
            make_float2(oacc[nt][2] * i1, oacc[nt][3] * i1);
    }
    if (qd == 0) {
        g_stats[(size_t)(b * NH + h) * TT + row0]     = make_float2(m0, l0);
        g_stats[(size_t)(b * NH + h) * TT + row0 + 8] = make_float2(m1, l1);
    }
}

// =============================================================================
// Pass 2: head-averaged attention map. Per (kc=64-col chunk, qt=128-row tile, b):
// loop heads, recompute S, p = exp(s/8 - m)/l, accumulate, write avg.
// Next head's K tile is prefetched into registers during compute.
// =============================================================================
__global__ void __launch_bounds__(256, 2)
avgmap_kernel(const float* __restrict__ q, const float* __restrict__ k,
              float* __restrict__ avg) {
    constexpr int PQ = 68;
    extern __shared__ uint32_t usm[];
    uint32_t* Qs = usm;                   // 128*68
    uint32_t* Ks = Qs + 128 * PQ;         // 64*68
    float2* St = (float2*)(Ks + 64 * PQ); // [8][128]

    const int kc = blockIdx.x, qt = blockIdx.y, b = blockIdx.z;
    const int tid = threadIdx.x, lane = tid & 31, w = tid >> 5;
    const int grp = lane >> 2, qd = lane & 3;
    const int wm = w >> 1, wn = w & 1;

    for (int j = tid; j < NH * 128; j += 256) {
        int h = j >> 7, r = j & 127;
        St[j] = g_stats[(size_t)(b * NH + h) * TT + qt * 128 + r];
    }

    float aacc[2][4][4];
#pragma unroll
    for (int mt = 0; mt < 2; mt++)
#pragma unroll
        for (int nt = 0; nt < 4; nt++)
#pragma unroll
            for (int i = 0; i < 4; i++) aacc[mt][nt][i] = 0.f;

    float4 kreg[4];
    auto ldgK = [&](int h) {
        const float* Kp = k + ((size_t)(b * TT) + kc * 64) * CC + h * 64;
#pragma unroll
        for (int i = 0; i < 4; i++) {
            int j = i * 256 + tid;
            int r = j >> 4, c4 = (j & 15) << 2;
            kreg[i] = *(const float4*)(Kp + (size_t)r * CC + c4);
        }
    };
    ldgK(0);

    for (int h = 0; h < NH; h++) {
        __syncthreads();   // buffers free (compute h-1 done; no-op at h=0)
        // commit prefetched K tile
#pragma unroll
        for (int i = 0; i < 4; i++) {
            int j = i * 256 + tid;
            int r = j >> 4, c4 = (j & 15) << 2;
            uint4 u;
            u.x = f2tf32(kreg[i].x); u.y = f2tf32(kreg[i].y);
            u.z = f2tf32(kreg[i].z); u.w = f2tf32(kreg[i].w);
            *(uint4*)(Ks + r * PQ + c4) = u;
        }
        // stage Q for this head (synchronous)
        {
            const float* Qp = q + ((size_t)(b * TT) + qt * 128) * CC + h * 64;
#pragma unroll
            for (int i = 0; i < 8; i++) {
                int j = i * 256 + tid;
                int r = j >> 4, c4 = (j & 15) << 2;
                float4 t4 = *(const float4*)(Qp + (size_t)r * CC + c4);
                uint4 u;
                u.x = f2tf32(t4.x); u.y = f2tf32(t4.y);
                u.z = f2tf32(t4.z); u.w = f2tf32(t4.w);
                *(uint4*)(Qs + r * PQ + c4) = u;
            }
        }
        if (h + 1 < NH) ldgK(h + 1);   // prefetch next head's K
        __syncthreads();

        float sacc[2][4][4];
#pragma unroll
        for (int mt = 0; mt < 2; mt++)
#pragma unroll
            for (int nt = 0; nt < 4; nt++)
#pragma unroll
                for (int i = 0; i < 4; i++) sacc[mt][nt][i] = 0.f;

#pragma unroll
        for (int k8 = 0; k8 < 8; k8++) {
            uint32_t af[2][4];
#pragma unroll
            for (int mt = 0; mt < 2; mt++) {
                int r0 = wm * 32 + mt * 16 + grp;
                af[mt][0] = Qs[(r0)     * PQ + k8 * 8 + qd];
                af[mt][1] = Qs[(r0 + 8) * PQ + k8 * 8 + qd];
                af[mt][2] = Qs[(r0)     * PQ + k8 * 8 + qd + 4];
                af[mt][3] = Qs[(r0 + 8) * PQ + k8 * 8 + qd + 4];
            }
#pragma unroll
            for (int nt = 0; nt < 4; nt++) {
                int nb = wn * 32 + nt * 8 + grp;
                uint32_t bf[2];
                bf[0] = Ks[nb * PQ + k8 * 8 + qd];
                bf[1] = Ks[nb * PQ + k8 * 8 + qd + 4];
#pragma unroll
                for (int mt = 0; mt < 2; mt++)
                    mma_tf32(sacc[mt][nt], af[mt], bf);
            }
        }

        // p = exp(s/8 - m) / l, accumulate over heads
#pragma unroll
        for (int mt = 0; mt < 2; mt++) {
            int r0 = wm * 32 + mt * 16 + grp;
            float2 s0 = St[h * 128 + r0];
            float2 s1 = St[h * 128 + r0 + 8];
            float il0 = 1.f / s0.y, il1 = 1.f / s1.y;
#pragma unroll
            for (int nt = 0; nt < 4; nt++) {
                aacc[mt][nt][0] += __expf(0.125f * sacc[mt][nt][0] - s0.x) * il0;
                aacc[mt][nt][1] += __expf(0.125f * sacc[mt][nt][1] - s0.x) * il0;
                aacc[mt][nt][2] += __expf(0.125f * sacc[mt][nt][2] - s1.x) * il1;
                aacc[mt][nt][3] += __expf(0.125f * sacc[mt][nt][3] - s1.x) * il1;
            }
        }
    }

    const float inv8 = 1.0f / NH;
#pragma unroll
    for (int mt = 0; mt < 2; mt++) {
        int qrow = qt * 128 + wm * 32 + mt * 16 + grp;
        int kcol = kc * 64 + wn * 32;
        float* A0 = avg + ((size_t)(b * TT) + qrow) * TT + kcol;
        float* A1 = A0 + (size_t)8 * TT;
#pragma unroll
        for (int nt = 0; nt < 4; nt++) {
            *(float2*)(A0 + nt * 8 + qd * 2) =
                make_float2(aacc[mt][nt][0] * inv8, aacc[mt][nt][1] * inv8);
            *(float2*)(A1 + nt * 8 + qd * 2) =
                make_float2(aacc[mt][nt][2] * inv8, aacc[mt][nt][3] * inv8);
        }
    }
}

// ---------------- embedding + positional ------------------------------------
__global__ void embed_kernel(const int* __restrict__ x,
                             const float* __restrict__ emb,
                             const float* __restrict__ pos,
                             float* __restrict__ out) {
    int idx = blockIdx.x * blockDim.x + threadIdx.x;
    if (idx >= MT * CC) return;
    int c  = idx % CC;
    int bt = idx / CC;
    int t  = bt % TT;
    int tok = x[bt];
    if (tok < 0) tok = 0;
    if (tok >= VOCAB) tok = VOCAB - 1;
    out[idx] = emb[(size_t)tok * CC + c] + pos[(size_t)t * CC + c];
}

// ---------------- layernorm: one warp per 512-float row ----------------------
__global__ void ln_kernel(const float* __restrict__ in,
                          const float* __restrict__ g,
                          const float* __restrict__ b,
                          float* __restrict__ out) {
    int row  = blockIdx.x * 8 + (threadIdx.x >> 5);
    int lane = threadIdx.x & 31;
    const float4* xr = (const float4*)(in + (size_t)row * CC);
    float4 v[4];
    float s = 0.f;
#pragma unroll
    for (int i = 0; i < 4; i++) {
        v[i] = xr[i * 32 + lane];
        s += v[i].x + v[i].y + v[i].z + v[i].w;
    }
#pragma unroll
    for (int o = 16; o; o >>= 1) s += __shfl_xor_sync(0xffffffffu, s, o);
    float mean = s * (1.0f / CC);
    float var = 0.f;
#pragma unroll
    for (int i = 0; i < 4; i++) {
        float dx = v[i].x - mean, dy = v[i].y - mean, dz = v[i].z - mean, dw = v[i].w - mean;
        var += dx * dx + dy * dy + dz * dz + dw * dw;
    }
#pragma unroll
    for (int o = 16; o; o >>= 1) var += __shfl_xor_sync(0xffffffffu, var, o);
    float rstd = rsqrtf(var * (1.0f / CC) + 1e-5f);
    float4* op = (float4*)(out + (size_t)row * CC);
    const float4* gp = (const float4*)g;
    const float4* bp = (const float4*)b;
#pragma unroll
    for (int i = 0; i < 4; i++) {
        float4 gg = gp[i * 32 + lane], bb = bp[i * 32 + lane];
        float4 o4;
        o4.x = (v[i].x - mean) * rstd * gg.x + bb.x;
        o4.y = (v[i].y - mean) * rstd * gg.y + bb.y;
        o4.z = (v[i].z - mean) * rstd * gg.z + bb.z;
        o4.w = (v[i].w - mean) * rstd * gg.w + bb.w;
        op[i * 32 + lane] = o4;
    }
}

// ---------------- final pooled output: mean over T of lnf(x) ----------------
__global__ void final_mean_kernel(const float* __restrict__ hln,
                                  float* __restrict__ out) {
    int bd = blockIdx.x;
    int b = bd / CC, d = bd % CC;
    __shared__ float red[256];
    int tid = threadIdx.x;
    float s = 0.f;
    for (int t = tid; t < TT; t += 256)
        s += hln[((size_t)b * TT + t) * CC + d];
    red[tid] = s; __syncthreads();
    for (int o = 128; o > 0; o >>= 1) { if (tid < o) red[tid] += red[tid + o]; __syncthreads(); }
    if (tid == 0) out[bd] = red[0] * (1.0f / TT);
}

// ---------------- launch ------------------------------------------------------
extern "C" void kernel_launch(void* const* d_in, const int* in_sizes, int n_in,
                              void* d_out, int out_size) {
    const int* x      = (const int*)d_in[0];
    const float* emb  = (const float*)d_in[1];
    const float* pos  = (const float*)d_in[2];
    const float* Wq = (const float*)d_in[3],  *bq = (const float*)d_in[4];
    const float* Wk = (const float*)d_in[5],  *bk = (const float*)d_in[6];
    const float* Wv = (const float*)d_in[7],  *bv = (const float*)d_in[8];
    const float* Wo = (const float*)d_in[9],  *bo = (const float*)d_in[10];
    const float* W1 = (const float*)d_in[11], *b1 = (const float*)d_in[12];
    const float* W2 = (const float*)d_in[13], *b2 = (const float*)d_in[14];
    const float* ln1g = (const float*)d_in[15], *ln1b = (const float*)d_in[16];
    const float* ln2g = (const float*)d_in[17], *ln2b = (const float*)d_in[18];
    const float* lnfg = (const float*)d_in[19], *lnfb = (const float*)d_in[20];
    float* out = (float*)d_out;

    float *xb, *lnb, *qb, *kb, *vb, *ab, *fb;
    cudaGetSymbolAddress((void**)&xb,  g_x);
    cudaGetSymbolAddress((void**)&lnb, g_ln);
    cudaGetSymbolAddress((void**)&qb,  g_q);
    cudaGetSymbolAddress((void**)&kb,  g_k);
    cudaGetSymbolAddress((void**)&vb,  g_v);
    cudaGetSymbolAddress((void**)&ab,  g_attn);
    cudaGetSymbolAddress((void**)&fb,  g_ff);

    const int SM_128_128 = (2 * 128 * 36 + 2 * 128 * 36) * 4;                 // 73728
    const int SM_64_128  = (2 * 64 * 36 + 2 * 128 * 36) * 4;                  // 55296
    const int SM_FLASH   = (128 * 68 + 32 * 68 + 32 * 72 + 128 * 36) * 4;     // 71168
    const int SM_AVG     = (128 * 68 + 64 * 68) * 4 + NH * 128 * 8;           // 60416

    cudaFuncSetAttribute((const void*)gemm_qkv_kernel<128, 128>,
                         cudaFuncAttributeMaxDynamicSharedMemorySize, SM_128_128);
    cudaFuncSetAttribute((const void*)gemm_tc_kernel<2, 128, 128>,
                         cudaFuncAttributeMaxDynamicSharedMemorySize, SM_128_128);
    cudaFuncSetAttribute((const void*)gemm_tc_kernel<3, 64, 128>,
                         cudaFuncAttributeMaxDynamicSharedMemorySize, SM_64_128);
    cudaFuncSetAttribute((const void*)flash_kernel,
                         cudaFuncAttributeMaxDynamicSharedMemorySize, SM_FLASH);
    cudaFuncSetAttribute((const void*)avgmap_kernel,
                         cudaFuncAttributeMaxDynamicSharedMemorySize, SM_AVG);

    const size_t attn_elems = (size_t)NLAYER * BB * TT * TT;
    float* attn_out = out + ((size_t)out_size - attn_elems);

    embed_kernel<<<(MT * CC + 255) / 256, 256>>>(x, emb, pos, xb);

    for (int l = 0; l < NLAYER; l++) {
        const float* wq = Wq + (size_t)l * CC * CC;
        const float* wk = Wk + (size_t)l * CC * CC;
        const float* wv = Wv + (size_t)l * CC * CC;
        const float* wo = Wo + (size_t)l * CC * CC;
        const float* w1 = W1 + (size_t)l * FF * CC;
        const float* w2 = W2 + (size_t)l * CC * FF;

        ln_kernel<<<MT / 8, 256>>>(xb, ln1g + (size_t)l * CC, ln1b + (size_t)l * CC, lnb);

        dim3 gqkv(CC / 128, MT / 128, 3);
        gemm_qkv_kernel<128, 128><<<gqkv, 256, SM_128_128>>>(
            lnb, wq, wk, wv,
            bq + (size_t)l * CC, bk + (size_t)l * CC, bv + (size_t)l * CC,
            qb, kb, vb);

        // fused flash attention: O + stats
        dim3 gfl(TT / 128, NH, BB);
        flash_kernel<<<gfl, 256, SM_FLASH>>>(qb, kb, vb, ab);

        // head-averaged attention map
        dim3 gav(TT / 64, TT / 128, BB);
        avgmap_kernel<<<gav, 256, SM_AVG>>>(qb, kb, attn_out + (size_t)l * BB * TT * TT);

        // Wo projection + residual
        dim3 gwo(CC / 128, MT / 64, 1);
        gemm_tc_kernel<3, 64, 128><<<gwo, 256, SM_64_128>>>(
            ab, wo, bo + (size_t)l * CC, xb, xb, CC, CC, CC, CC);

        ln_kernel<<<MT / 8, 256>>>(xb, ln2g + (size_t)l * CC, ln2b + (size_t)l * CC, lnb);

        // FFN1 + relu
        dim3 gf1(FF / 128, MT / 128, 1);
        gemm_tc_kernel<2, 128, 128><<<gf1, 256, SM_128_128>>>(
            lnb, w1, b1 + (size_t)l * FF, nullptr, fb, CC, CC, FF, CC);

        // FFN2 + residual
        dim3 gf2(CC / 128, MT / 64, 1);
        gemm_tc_kernel<3, 64, 128><<<gf2, 256, SM_64_128>>>(
            fb, w2, b2 + (size_t)l * CC, xb, xb, FF, FF, CC, FF);
    }

    ln_kernel<<<MT / 8, 256>>>(xb, lnfg, lnfb, lnb);
    final_mean_kernel<<<BB * CC, 256>>>(lnb, out);
}

// round 8
// speedup vs baseline: 1.0467x; 1.0467x over previous
#include <cuda_runtime.h>
#include <math.h>
#include <stdint.h>

#define NLAYER 4
#define BB 2
#define TT 2048
#define CC 512
#define NH 8
#define HDIM 64
#define FF 2048
#define VOCAB 32000
#define MT (BB*TT)   // 4096 rows

// ---------------- scratch (device globals; no allocations allowed) ----------
__device__ float g_x   [(size_t)MT*CC];
__device__ float g_ln  [(size_t)MT*CC];
__device__ float g_q   [(size_t)MT*CC];
__device__ float g_k   [(size_t)MT*CC];
__device__ float g_v   [(size_t)MT*CC];
__device__ float g_attn[(size_t)MT*CC];
__device__ float g_ff  [(size_t)MT*FF];
__device__ float2 g_stats[(size_t)BB*NH*TT];   // per-row (m, l) from flash pass

// ---------------- helpers ----------------------------------------------------
__device__ __forceinline__ uint32_t f2tf32(float x) {
    uint32_t u;
    asm("cvt.rna.tf32.f32 %0, %1;" : "=r"(u) : "f"(x));
    return u;
}

__device__ __forceinline__ void mma_tf32(float* c, const uint32_t* a, const uint32_t* b) {
    asm volatile(
        "mma.sync.aligned.m16n8k8.row.col.f32.tf32.tf32.f32 "
        "{%0,%1,%2,%3}, {%4,%5,%6,%7}, {%8,%9}, {%0,%1,%2,%3};"
        : "+f"(c[0]), "+f"(c[1]), "+f"(c[2]), "+f"(c[3])
        : "r"(a[0]), "r"(a[1]), "r"(a[2]), "r"(a[3]), "r"(b[0]), "r"(b[1]));
}

__device__ __forceinline__ void cp16(void* sdst, const void* gsrc) {
    unsigned s = (unsigned)__cvta_generic_to_shared(sdst);
    asm volatile("cp.async.cg.shared.global [%0], [%1], 16;\n" :: "r"(s), "l"(gsrc));
}
__device__ __forceinline__ void cp_commit() { asm volatile("cp.async.commit_group;\n"); }
template<int N>
__device__ __forceinline__ void cp_wait() { asm volatile("cp.async.wait_group %0;\n" :: "n"(N)); }

// =============================================================================
// TF32 tensor-core GEMM core (NT). C[M,N] = A[M,K] @ W[N,K]^T
// CTA tile BM x BN x 32, 256 threads, double-buffered cp.async pipeline.
// EPI: 1 = +bias, 2 = +bias,relu, 3 = +bias,+residual
// =============================================================================
template<int EPI, int BM, int BN>
__device__ __forceinline__ void gemm_core(
    const float* __restrict__ A, const float* __restrict__ B,
    const float* __restrict__ bias, const float* __restrict__ res,
    float* __restrict__ C, int lda, int ldb, int ldc, int K)
{
    constexpr int WM   = BM / 64;
    constexpr int WN   = 8 / WM;
    constexpr int NCW  = BN / WN;
    constexpr int NT_  = NCW / 8;

    extern __shared__ float smem[];
    float* As = smem;                        // 2 * BM * 36
    float* Bs = smem + 2 * BM * 36;          // 2 * BN * 36

    const int tid  = threadIdx.x;
    const int lane = tid & 31, wid = tid >> 5;
    const int warpM = (WM == 1) ? 0 : (wid & 1);
    const int warpN = (WM == 1) ? wid : (wid >> 1);
    const int grp = lane >> 2, qd = lane & 3;

    const int row0 = blockIdx.y * BM;
    const int col0 = blockIdx.x * BN;

    float acc[4][NT_][4];
#pragma unroll
    for (int mt = 0; mt < 4; mt++)
#pragma unroll
        for (int nt = 0; nt < NT_; nt++)
#pragma unroll
            for (int i = 0; i < 4; i++) acc[mt][nt][i] = 0.f;

    auto loadA = [&](int buf, int k0) {
#pragma unroll
        for (int i = 0; i < BM / 32; i++) {
            int idx = i * 256 + tid;
            int r = idx >> 3, c4 = (idx & 7) << 2;
            cp16(As + buf * BM * 36 + r * 36 + c4,
                 A + (size_t)(row0 + r) * lda + k0 + c4);
        }
    };
    auto loadB = [&](int buf, int k0) {
#pragma unroll
        for (int i = 0; i < BN / 32; i++) {
            int idx = i * 256 + tid;
            int r = idx >> 3, c4 = (idx & 7) << 2;
            cp16(Bs + buf * BN * 36 + r * 36 + c4,
                 B + (size_t)(col0 + r) * ldb + k0 + c4);
        }
    };

    auto compute = [&](int buf) {
        const float* Ab = As + buf * BM * 36;
        const float* Bb = Bs + buf * BN * 36;
#pragma unroll
        for (int kt = 0; kt < 4; kt++) {
            uint32_t af[4][4];
#pragma unroll
            for (int mt = 0; mt < 4; mt++) {
                int r0 = warpM * 64 + mt * 16 + grp;
                af[mt][0] = f2tf32(Ab[(r0)     * 36 + kt * 8 + qd]);
                af[mt][1] = f2tf32(Ab[(r0 + 8) * 36 + kt * 8 + qd]);
                af[mt][2] = f2tf32(Ab[(r0)     * 36 + kt * 8 + qd + 4]);
                af[mt][3] = f2tf32(Ab[(r0 + 8) * 36 + kt * 8 + qd + 4]);
            }
            uint32_t bf[NT_][2];
#pragma unroll
            for (int nt = 0; nt < NT_; nt++) {
                int nb = warpN * NCW + nt * 8 + grp;
                bf[nt][0] = f2tf32(Bb[nb * 36 + kt * 8 + qd]);
                bf[nt][1] = f2tf32(Bb[nb * 36 + kt * 8 + qd + 4]);
            }
#pragma unroll
            for (int mt = 0; mt < 4; mt++)
#pragma unroll
                for (int nt = 0; nt < NT_; nt++)
                    mma_tf32(acc[mt][nt], af[mt], bf[nt]);
        }
    };

    const int nk = K >> 5;
    loadA(0, 0);  loadB(0, 0);  cp_commit();
    loadA(1, 32); loadB(1, 32); cp_commit();
    cp_wait<1>();
    __syncthreads();

    for (int kb = 0; kb < nk; kb++) {
        compute(kb & 1);
        __syncthreads();
        if (kb + 2 < nk) { loadA(kb & 1, (kb + 2) * 32); loadB(kb & 1, (kb + 2) * 32); }
        cp_commit();
        cp_wait<1>();
        __syncthreads();
    }

#pragma unroll
    for (int mt = 0; mt < 4; mt++)
#pragma unroll
        for (int nt = 0; nt < NT_; nt++) {
            int row = row0 + warpM * 64 + mt * 16 + grp;
            int col = col0 + warpN * NCW + nt * 8 + qd * 2;
#pragma unroll
            for (int half = 0; half < 2; half++) {
                int r = row + half * 8;
                float v0 = acc[mt][nt][half * 2 + 0];
                float v1 = acc[mt][nt][half * 2 + 1];
                v0 += bias[col]; v1 += bias[col + 1];
                if (EPI == 2) { v0 = fmaxf(v0, 0.f); v1 = fmaxf(v1, 0.f); }
                if (EPI == 3) {
                    v0 += res[(size_t)r * ldc + col];
                    v1 += res[(size_t)r * ldc + col + 1];
                }
                *(float2*)(C + (size_t)r * ldc + col) = make_float2(v0, v1);
            }
        }
}

template<int EPI, int BM, int BN>
__global__ void __launch_bounds__(256, 2)
gemm_tc_kernel(const float* __restrict__ A, const float* __restrict__ B,
               const float* __restrict__ bias, const float* __restrict__ res,
               float* __restrict__ C, int lda, int ldb, int ldc, int K) {
    gemm_core<EPI, BM, BN>(A, B, bias, res, C, lda, ldb, ldc, K);
}

// ---- fused QKV (z selects weight/bias/output) --------------------------------
template<int BM, int BN>
__global__ void __launch_bounds__(256, 2)
gemm_qkv_kernel(const float* __restrict__ A,
                const float* __restrict__ Wq, const float* __restrict__ Wk,
                const float* __restrict__ Wv,
                const float* __restrict__ bq, const float* __restrict__ bk,
                const float* __restrict__ bv,
                float* __restrict__ q, float* __restrict__ k, float* __restrict__ v) {
    int z = blockIdx.z;
    const float* B    = z == 0 ? Wq : (z == 1 ? Wk : Wv);
    const float* bias = z == 0 ? bq : (z == 1 ? bk : bv);
    float* C          = z == 0 ? q  : (z == 1 ? k  : v);
    gemm_core<1, BM, BN>(A, B, bias, nullptr, C, CC, CC, CC, CC);
}

// =============================================================================
// Flash attention pass 1, v2.
// Per (qtile=128, h, b) CTA: 8 warps, warp = 16 rows.
// - Q fragments in REGISTERS (loop-invariant).
// - K fragment-packed SMEM (LDS.64 B-frags), stride-68 blocks, double-buffered.
// - V row-layout (stride 76) double-buffered; PV feeds the S accumulator
//   DIRECTLY as A-operand (register permute) with V rows pi-permuted at the
//   fragment load (pi(j)=2j / 2j-7 within each 8-block) -> no P SMEM at all.
// - ONE __syncthreads per key tile.
// =============================================================================
__global__ void __launch_bounds__(256, 2)
flash_kernel(const float* __restrict__ q, const float* __restrict__ k,
             const float* __restrict__ v, float* __restrict__ o) {
    constexpr int KT = 32, NKT = TT / KT;
    constexpr int KBLK = 68;      // Kf block stride (uints)
    constexpr int PV = 76;        // Vs row stride
    extern __shared__ uint32_t usm[];
    uint32_t* Kf = usm;                  // 2 * 32 * 68
    uint32_t* Vs = usm + 2 * 32 * KBLK;  // 2 * 32 * 76

    const int qt = blockIdx.x, h = blockIdx.y, b = blockIdx.z;
    const int tid = threadIdx.x, lane = tid & 31, w = tid >> 5;
    const int grp = lane >> 2, qd = lane & 3;
    const int rbase = w * 16;

    const float* Qp = q + ((size_t)(b * TT) + qt * 128) * CC + h * 64;
    const float* Kp = k + (size_t)b * TT * CC + h * 64;
    const float* Vp = v + (size_t)b * TT * CC + h * 64;

    // ---- Q fragments in registers, pre-scaled by 1/8 (exact) ----
    uint32_t qf[8][4];
#pragma unroll
    for (int k8 = 0; k8 < 8; k8++) {
        const float* Qr0 = Qp + (size_t)(rbase + grp) * CC + k8 * 8 + qd;
        const float* Qr1 = Qr0 + (size_t)8 * CC;
        qf[k8][0] = f2tf32(Qr0[0] * 0.125f);
        qf[k8][1] = f2tf32(Qr1[0] * 0.125f);
        qf[k8][2] = f2tf32(Qr0[4] * 0.125f);
        qf[k8][3] = f2tf32(Qr1[4] * 0.125f);
    }

    // staging coords
    const int skr = tid >> 3, skc = (tid & 7) * 8;    // K: one row, 8 cols
    const int svr = tid >> 4, svc = (tid & 15) * 4;   // V: rows svr, svr+16

    float4 kr0, kr1, vr0, vr1;
    auto ldgKV = [&](int kt) {
        const float* Kt = Kp + (size_t)(kt * KT + skr) * CC + skc;
        kr0 = *(const float4*)(Kt);
        kr1 = *(const float4*)(Kt + 4);
        const float* Vt = Vp + (size_t)(kt * KT) * CC + svc;
        vr0 = *(const float4*)(Vt + (size_t)svr * CC);
        vr1 = *(const float4*)(Vt + (size_t)(svr + 16) * CC);
    };
    auto stsKV = [&](int buf) {
        // K fragment-packed: blk = (key/8)*8 + (col/8); within blk: key%8 * 8,
        // order {j0,j4,j1,j5,j2,j6,j3,j7} = (qd*2 + pos) for j = qd + 4*pos
        uint32_t* kd = Kf + buf * 32 * KBLK
                     + ((skr >> 3) * 8 + (skc >> 3)) * KBLK + (skr & 7) * 8;
        uint4 ua, ub;
        ua.x = f2tf32(kr0.x); ua.y = f2tf32(kr1.x); ua.z = f2tf32(kr0.y); ua.w = f2tf32(kr1.y);
        ub.x = f2tf32(kr0.z); ub.y = f2tf32(kr1.z); ub.z = f2tf32(kr0.w); ub.w = f2tf32(kr1.w);
        *(uint4*)(kd)     = ua;
        *(uint4*)(kd + 4) = ub;
        uint32_t* vd = Vs + buf * 32 * PV;
        uint4 u;
        u.x = f2tf32(vr0.x); u.y = f2tf32(vr0.y); u.z = f2tf32(vr0.z); u.w = f2tf32(vr0.w);
        *(uint4*)(vd + svr * PV + svc) = u;
        u.x = f2tf32(vr1.x); u.y = f2tf32(vr1.y); u.z = f2tf32(vr1.z); u.w = f2tf32(vr1.w);
        *(uint4*)(vd + (svr + 16) * PV + svc) = u;
    };

    float oacc[8][4];
#pragma unroll
    for (int nt = 0; nt < 8; nt++)
#pragma unroll
        for (int i = 0; i < 4; i++) oacc[nt][i] = 0.f;
    float m0 = -1e30f, m1 = -1e30f, l0 = 0.f, l1 = 0.f;

    ldgKV(0);
    stsKV(0);
    __syncthreads();

    for (int kt = 0; kt < NKT; kt++) {
        const int buf = kt & 1;
        if (kt + 1 < NKT) ldgKV(kt + 1);

        const uint32_t* Kb = Kf + buf * 32 * KBLK;
        const uint32_t* Vb = Vs + buf * 32 * PV;

        // ---- S = Q @ K^T (16 rows x 32 keys) ----
        float sacc[4][4];
#pragma unroll
        for (int nt = 0; nt < 4; nt++)
#pragma unroll
            for (int i = 0; i < 4; i++) sacc[nt][i] = 0.f;
#pragma unroll
        for (int k8 = 0; k8 < 8; k8++) {
#pragma unroll
            for (int nt = 0; nt < 4; nt++) {
                uint2 p = *(const uint2*)(Kb + (nt * 8 + k8) * KBLK + grp * 8 + qd * 2);
                uint32_t bf[2] = {p.x, p.y};
                mma_tf32(sacc[nt], qf[k8], bf);
            }
        }

        // ---- online softmax update ----
        float mx0 = -1e30f, mx1 = -1e30f;
#pragma unroll
        for (int nt = 0; nt < 4; nt++) {
            mx0 = fmaxf(mx0, fmaxf(sacc[nt][0], sacc[nt][1]));
            mx1 = fmaxf(mx1, fmaxf(sacc[nt][2], sacc[nt][3]));
        }
        mx0 = fmaxf(mx0, __shfl_xor_sync(0xffffffffu, mx0, 1));
        mx0 = fmaxf(mx0, __shfl_xor_sync(0xffffffffu, mx0, 2));
        mx1 = fmaxf(mx1, __shfl_xor_sync(0xffffffffu, mx1, 1));
        mx1 = fmaxf(mx1, __shfl_xor_sync(0xffffffffu, mx1, 2));
        float mn0 = fmaxf(m0, mx0), mn1 = fmaxf(m1, mx1);
        float f0 = __expf(m0 - mn0), f1 = __expf(m1 - mn1);
        m0 = mn0; m1 = mn1;
        float rs0 = 0.f, rs1 = 0.f;
#pragma unroll
        for (int nt = 0; nt < 4; nt++) {
            sacc[nt][0] = __expf(sacc[nt][0] - m0);
            sacc[nt][1] = __expf(sacc[nt][1] - m0);
            sacc[nt][2] = __expf(sacc[nt][2] - m1);
            sacc[nt][3] = __expf(sacc[nt][3] - m1);
            rs0 += sacc[nt][0] + sacc[nt][1];
            rs1 += sacc[nt][2] + sacc[nt][3];
        }
        rs0 += __shfl_xor_sync(0xffffffffu, rs0, 1);
        rs0 += __shfl_xor_sync(0xffffffffu, rs0, 2);
        rs1 += __shfl_xor_sync(0xffffffffu, rs1, 1);
        rs1 += __shfl_xor_sync(0xffffffffu, rs1, 2);
        l0 = l0 * f0 + rs0;
        l1 = l1 * f1 + rs1;
#pragma unroll
        for (int nt = 0; nt < 8; nt++) {
            oacc[nt][0] *= f0; oacc[nt][1] *= f0;
            oacc[nt][2] *= f1; oacc[nt][3] *= f1;
        }

        // ---- O += P @ V : S-accumulator fed directly as A-operand ----
        // A-frag order (c0, c2, c1, c3); V rows pi-permuted at load:
        // b0 = V[kb*8 + 2qd][n], b1 = V[kb*8 + 2qd + 1][n]
#pragma unroll
        for (int kb = 0; kb < 4; kb++) {
            uint32_t af[4];
            af[0] = f2tf32(sacc[kb][0]);
            af[1] = f2tf32(sacc[kb][2]);
            af[2] = f2tf32(sacc[kb][1]);
            af[3] = f2tf32(sacc[kb][3]);
#pragma unroll
            for (int nt = 0; nt < 8; nt++) {
                uint32_t bf[2];
                bf[0] = Vb[(kb * 8 + 2 * qd)     * PV + nt * 8 + grp];
                bf[1] = Vb[(kb * 8 + 2 * qd + 1) * PV + nt * 8 + grp];
                mma_tf32(oacc[nt], af, bf);
            }
        }

        if (kt + 1 < NKT) stsKV(buf ^ 1);
        __syncthreads();
    }

    // ---- epilogue: normalize + write O and stats ----
    float i0 = 1.f / l0, i1 = 1.f / l1;
    int row0 = qt * 128 + rbase + grp;
    float* Op = o + ((size_t)(b * TT) + row0) * CC + h * 64;
#pragma unroll
    for (int nt = 0; nt < 8; nt++) {
        *(float2*)(Op + nt * 8 + qd * 2) =
            make_float2(oacc[nt][0] * i0, oacc[nt][1] * i0);
        *(float2*)(Op + (size_t)8 * CC + nt * 8 + qd * 2) =
            make_float2(oacc[nt][2] * i1, oacc[nt][3] * i1);
    }
    if (qd == 0) {
        g_stats[(size_t)(b * NH + h) * TT + row0]     = make_float2(m0, l0);
        g_stats[(size_t)(b * NH + h) * TT + row0 + 8] = make_float2(m1, l1);
    }
}

// =============================================================================
// Pass 2: head-averaged attention map, fragment-packed.
// Per (kc=64-col chunk, qt=128-row tile, b) CTA: loop heads, recompute S,
// p = exp(s/8 - m)/l, accumulate, write avg.
// Q quads -> LDS.128 A-frags; K pairs -> LDS.64 B-frags. K reg-prefetched.
// =============================================================================
__global__ void __launch_bounds__(256, 2)
avgmap_kernel(const float* __restrict__ q, const float* __restrict__ k,
              float* __restrict__ avg) {
    constexpr int QBLK = 132, KBLK = 68;
    extern __shared__ uint32_t usm[];
    uint32_t* QF = usm;                    // 64 blocks * 132
    uint32_t* KF = usm + 64 * QBLK;        // 64 blocks * 68
    float2* St = (float2*)(usm + 64 * QBLK + 64 * KBLK);  // [8][128]

    const int kc = blockIdx.x, qt = blockIdx.y, b = blockIdx.z;
    const int tid = threadIdx.x, lane = tid & 31, w = tid >> 5;
    const int grp = lane >> 2, qd = lane & 3;
    const int wm = w >> 1, wn = w & 1;

    for (int j = tid; j < NH * 128; j += 256)
        St[j] = g_stats[(size_t)(b * NH + (j >> 7)) * TT + qt * 128 + (j & 127)];

    float aacc[2][4][4];
#pragma unroll
    for (int mt = 0; mt < 2; mt++)
#pragma unroll
        for (int nt = 0; nt < 4; nt++)
#pragma unroll
            for (int i = 0; i < 4; i++) aacc[mt][nt][i] = 0.f;

    const int kkr = tid >> 2, kc0 = (tid & 3) * 16;   // K: one row, 16 cols
    float4 kreg[4];
    auto ldgK = [&](int h) {
        const float* Kp = k + ((size_t)(b * TT) + kc * 64 + kkr) * CC + h * 64 + kc0;
#pragma unroll
        for (int i = 0; i < 4; i++) kreg[i] = *(const float4*)(Kp + i * 4);
    };
    ldgK(0);

    for (int h = 0; h < NH; h++) {
        __syncthreads();   // prev compute done with QF/KF
        // ---- commit prefetched K tile, fragment-packed ----
        {
            uint32_t* kb0 = KF + ((kkr >> 3) * 8 + (kc0 >> 3)) * KBLK + (kkr & 7) * 8;
#pragma unroll
            for (int bb = 0; bb < 2; bb++) {
                float4 f0 = kreg[bb * 2], f1 = kreg[bb * 2 + 1];
                uint4 ua, ub;
                ua.x = f2tf32(f0.x); ua.y = f2tf32(f1.x); ua.z = f2tf32(f0.y); ua.w = f2tf32(f1.y);
                ub.x = f2tf32(f0.z); ub.y = f2tf32(f1.z); ub.z = f2tf32(f0.w); ub.w = f2tf32(f1.w);
                *(uint4*)(kb0 + bb * KBLK)     = ua;
                *(uint4*)(kb0 + bb * KBLK + 4) = ub;
            }
        }
        // ---- stage Q for head h, quad-packed (scatter STS.32) ----
        {
            const float* Qp = q + ((size_t)(b * TT) + qt * 128) * CC + h * 64;
#pragma unroll
            for (int i = 0; i < 8; i++) {
                int j = i * 256 + tid;
                int r = j >> 4, c4 = (j & 15) << 2;
                float4 t4 = *(const float4*)(Qp + (size_t)r * CC + c4);
                int blk  = (r >> 4) * 8 + (c4 >> 3);
                int base = blk * QBLK + ((c4 >> 2) & 1) * 2 + ((r >> 3) & 1);
                int ro   = (r & 7) * 4;
                QF[base + (ro + 0) * 4] = f2tf32(t4.x);
                QF[base + (ro + 1) * 4] = f2tf32(t4.y);
                QF[base + (ro + 2) * 4] = f2tf32(t4.z);
                QF[base + (ro + 3) * 4] = f2tf32(t4.w);
            }
        }
        if (h + 1 < NH) ldgK(h + 1);
        __syncthreads();

        float sacc[2][4][4];
#pragma unroll
        for (int mt = 0; mt < 2; mt++)
#pragma unroll
            for (int nt = 0; nt < 4; nt++)
#pragma unroll
                for (int i = 0; i < 4; i++) sacc[mt][nt][i] = 0.f;

#pragma unroll
        for (int k8 = 0; k8 < 8; k8++) {
            uint32_t af[2][4];
#pragma unroll
            for (int mt = 0; mt < 2; mt++) {
                uint4 u = *(const uint4*)(QF + ((wm * 2 + mt) * 8 + k8) * QBLK
                                          + (grp * 4 + qd) * 4);
                af[mt][0] = u.x; af[mt][1] = u.y; af[mt][2] = u.z; af[mt][3] = u.w;
            }
#pragma unroll
            for (int nt = 0; nt < 4; nt++) {
                uint2 p = *(const uint2*)(KF + ((wn * 4 + nt) * 8 + k8) * KBLK
                                          + grp * 8 + qd * 2);
                uint32_t bf[2] = {p.x, p.y};
                mma_tf32(sacc[0][nt], af[0], bf);
                mma_tf32(sacc[1][nt], af[1], bf);
            }
        }

        // p = exp(s/8 - m) / l, accumulate over heads
#pragma unroll
        for (int mt = 0; mt < 2; mt++) {
            int r0 = wm * 32 + mt * 16 + grp;
            float2 s0 = St[h * 128 + r0];
            float2 s1 = St[h * 128 + r0 + 8];
            float il0 = 1.f / s0.y, il1 = 1.f / s1.y;
#pragma unroll
            for (int nt = 0; nt < 4; nt++) {
                aacc[mt][nt][0] += __expf(0.125f * sacc[mt][nt][0] - s0.x) * il0;
                aacc[mt][nt][1] += __expf(0.125f * sacc[mt][nt][1] - s0.x) * il0;
                aacc[mt][nt][2] += __expf(0.125f * sacc[mt][nt][2] - s1.x) * il1;
                aacc[mt][nt][3] += __expf(0.125f * sacc[mt][nt][3] - s1.x) * il1;
            }
        }
    }

    const float inv8 = 1.0f / NH;
#pragma unroll
    for (int mt = 0; mt < 2; mt++) {
        int qrow = qt * 128 + wm * 32 + mt * 16 + grp;
        int kcol = kc * 64 + wn * 32;
        float* A0 = avg + ((size_t)(b * TT) + qrow) * TT + kcol;
        float* A1 = A0 + (size_t)8 * TT;
#pragma unroll
        for (int nt = 0; nt < 4; nt++) {
            *(float2*)(A0 + nt * 8 + qd * 2) =
                make_float2(aacc[mt][nt][0] * inv8, aacc[mt][nt][1] * inv8);
            *(float2*)(A1 + nt * 8 + qd * 2) =
                make_float2(aacc[mt][nt][2] * inv8, aacc[mt][nt][3] * inv8);
        }
    }
}

// ---------------- embedding + positional ------------------------------------
__global__ void embed_kernel(const int* __restrict__ x,
                             const float* __restrict__ emb,
                             const float* __restrict__ pos,
                             float* __restrict__ out) {
    int idx = blockIdx.x * blockDim.x + threadIdx.x;
    if (idx >= MT * CC) return;
    int c  = idx % CC;
    int bt = idx / CC;
    int t  = bt % TT;
    int tok = x[bt];
    if (tok < 0) tok = 0;
    if (tok >= VOCAB) tok = VOCAB - 1;
    out[idx] = emb[(size_t)tok * CC + c] + pos[(size_t)t * CC + c];
}

// ---------------- layernorm: one warp per 512-float row ----------------------
__global__ void ln_kernel(const float* __restrict__ in,
                          const float* __restrict__ g,
                          const float* __restrict__ b,
                          float* __restrict__ out) {
    int row  = blockIdx.x * 8 + (threadIdx.x >> 5);
    int lane = threadIdx.x & 31;
    const float4* xr = (const float4*)(in + (size_t)row * CC);
    float4 v[4];
    float s = 0.f;
#pragma unroll
    for (int i = 0; i < 4; i++) {
        v[i] = xr[i * 32 + lane];
        s += v[i].x + v[i].y + v[i].z + v[i].w;
    }
#pragma unroll
    for (int o = 16; o; o >>= 1) s += __shfl_xor_sync(0xffffffffu, s, o);
    float mean = s * (1.0f / CC);
    float var = 0.f;
#pragma unroll
    for (int i = 0; i < 4; i++) {
        float dx = v[i].x - mean, dy = v[i].y - mean, dz = v[i].z - mean, dw = v[i].w - mean;
        var += dx * dx + dy * dy + dz * dz + dw * dw;
    }
#pragma unroll
    for (int o = 16; o; o >>= 1) var += __shfl_xor_sync(0xffffffffu, var, o);
    float rstd = rsqrtf(var * (1.0f / CC) + 1e-5f);
    float4* op = (float4*)(out + (size_t)row * CC);
    const float4* gp = (const float4*)g;
    const float4* bp = (const float4*)b;
#pragma unroll
    for (int i = 0; i < 4; i++) {
        float4 gg = gp[i * 32 + lane], bb = bp[i * 32 + lane];
        float4 o4;
        o4.x = (v[i].x - mean) * rstd * gg.x + bb.x;
        o4.y = (v[i].y - mean) * rstd * gg.y + bb.y;
        o4.z = (v[i].z - mean) * rstd * gg.z + bb.z;
        o4.w = (v[i].w - mean) * rstd * gg.w + bb.w;
        op[i * 32 + lane] = o4;
    }
}

// ---------------- final pooled output: mean over T of lnf(x) ----------------
__global__ void final_mean_kernel(const float* __restrict__ hln,
                                  float* __restrict__ out) {
    int bd = blockIdx.x;
    int b = bd / CC, d = bd % CC;
    __shared__ float red[256];
    int tid = threadIdx.x;
    float s = 0.f;
    for (int t = tid; t < TT; t += 256)
        s += hln[((size_t)b * TT + t) * CC + d];
    red[tid] = s; __syncthreads();
    for (int o = 128; o > 0; o >>= 1) { if (tid < o) red[tid] += red[tid + o]; __syncthreads(); }
    if (tid == 0) out[bd] = red[0] * (1.0f / TT);
}

// ---------------- launch ------------------------------------------------------
extern "C" void kernel_launch(void* const* d_in, const int* in_sizes, int n_in,
                              void* d_out, int out_size) {
    const int* x      = (const int*)d_in[0];
    const float* emb  = (const float*)d_in[1];
    const float* pos  = (const float*)d_in[2];
    const float* Wq = (const float*)d_in[3],  *bq = (const float*)d_in[4];
    const float* Wk = (const float*)d_in[5],  *bk = (const float*)d_in[6];
    const float* Wv = (const float*)d_in[7],  *bv = (const float*)d_in[8];
    const float* Wo = (const float*)d_in[9],  *bo = (const float*)d_in[10];
    const float* W1 = (const float*)d_in[11], *b1 = (const float*)d_in[12];
    const float* W2 = (const float*)d_in[13], *b2 = (const float*)d_in[14];
    const float* ln1g = (const float*)d_in[15], *ln1b = (const float*)d_in[16];
    const float* ln2g = (const float*)d_in[17], *ln2b = (const float*)d_in[18];
    const float* lnfg = (const float*)d_in[19], *lnfb = (const float*)d_in[20];
    float* out = (float*)d_out;

    float *xb, *lnb, *qb, *kb, *vb, *ab, *fb;
    cudaGetSymbolAddress((void**)&xb,  g_x);
    cudaGetSymbolAddress((void**)&lnb, g_ln);
    cudaGetSymbolAddress((void**)&qb,  g_q);
    cudaGetSymbolAddress((void**)&kb,  g_k);
    cudaGetSymbolAddress((void**)&vb,  g_v);
    cudaGetSymbolAddress((void**)&ab,  g_attn);
    cudaGetSymbolAddress((void**)&fb,  g_ff);

    const int SM_128_128 = (2 * 128 * 36 + 2 * 128 * 36) * 4;           // 73728
    const int SM_64_128  = (2 * 64 * 36 + 2 * 128 * 36) * 4;            // 55296
    const int SM_FLASH   = (2 * 32 * 68 + 2 * 32 * 76) * 4;             // 36864
    const int SM_AVG     = (64 * 132 + 64 * 68) * 4 + NH * 128 * 8;     // 59392

    cudaFuncSetAttribute((const void*)gemm_qkv_kernel<128, 128>,
                         cudaFuncAttributeMaxDynamicSharedMemorySize, SM_128_128);
    cudaFuncSetAttribute((const void*)gemm_tc_kernel<2, 128, 128>,
                         cudaFuncAttributeMaxDynamicSharedMemorySize, SM_128_128);
    cudaFuncSetAttribute((const void*)gemm_tc_kernel<3, 64, 128>,
                         cudaFuncAttributeMaxDynamicSharedMemorySize, SM_64_128);
    cudaFuncSetAttribute((const void*)flash_kernel,
                         cudaFuncAttributeMaxDynamicSharedMemorySize, SM_FLASH);
    cudaFuncSetAttribute((const void*)avgmap_kernel,
                         cudaFuncAttributeMaxDynamicSharedMemorySize, SM_AVG);

    const size_t attn_elems = (size_t)NLAYER * BB * TT * TT;
    float* attn_out = out + ((size_t)out_size - attn_elems);

    embed_kernel<<<(MT * CC + 255) / 256, 256>>>(x, emb, pos, xb);

    for (int l = 0; l < NLAYER; l++) {
        const float* wq = Wq + (size_t)l * CC * CC;
        const float* wk = Wk + (size_t)l * CC * CC;
        const float* wv = Wv + (size_t)l * CC * CC;
        const float* wo = Wo + (size_t)l * CC * CC;
        const float* w1 = W1 + (size_t)l * FF * CC;
        const float* w2 = W2 + (size_t)l * CC * FF;

        ln_kernel<<<MT / 8, 256>>>(xb, ln1g + (size_t)l * CC, ln1b + (size_t)l * CC, lnb);

        dim3 gqkv(CC / 128, MT / 128, 3);
        gemm_qkv_kernel<128, 128><<<gqkv, 256, SM_128_128>>>(
            lnb, wq, wk, wv,
            bq + (size_t)l * CC, bk + (size_t)l * CC, bv + (size_t)l * CC,
            qb, kb, vb);

        // fused flash attention: O + stats
        dim3 gfl(TT / 128, NH, BB);
        flash_kernel<<<gfl, 256, SM_FLASH>>>(qb, kb, vb, ab);

        // head-averaged attention map
        dim3 gav(TT / 64, TT / 128, BB);
        avgmap_kernel<<<gav, 256, SM_AVG>>>(qb, kb, attn_out + (size_t)l * BB * TT * TT);

        // Wo projection + residual
        dim3 gwo(CC / 128, MT / 64, 1);
        gemm_tc_kernel<3, 64, 128><<<gwo, 256, SM_64_128>>>(
            ab, wo, bo + (size_t)l * CC, xb, xb, CC, CC, CC, CC);

        ln_kernel<<<MT / 8, 256>>>(xb, ln2g + (size_t)l * CC, ln2b + (size_t)l * CC, lnb);

        // FFN1 + relu
        dim3 gf1(FF / 128, MT / 128, 1);
        gemm_tc_kernel<2, 128, 128><<<gf1, 256, SM_128_128>>>(
            lnb, w1, b1 + (size_t)l * FF, nullptr, fb, CC, CC, FF, CC);

        // FFN2 + residual
        dim3 gf2(CC / 128, MT / 64, 1);
        gemm_tc_kernel<3, 64, 128><<<gf2, 256, SM_64_128>>>(
            fb, w2, b2 + (size_t)l * CC, xb, xb, FF, FF, CC, FF);
    }

    ln_kernel<<<MT / 8, 256>>>(xb, lnfg, lnfb, lnb);
    final_mean_kernel<<<BB * CC, 256>>>(lnb, out);
}